// round 15
// baseline (speedup 1.0000x reference)
#include <cuda_runtime.h>
#include <cuda_fp16.h>
#include <cstdint>

// ---------------- problem constants -----------------------------------------
#define NF     128           // node features == H*D
#define MAXN   50000
#define XP     50176         // g_xT pitch (nodes, padded)
#define MAXE   800000
#define TILE_M 128           // nodes per CTA
#define NIT    32            // K iterations (128 features / 4 per iter)
#define BPITCH 56            // fp16 col pitch (112 bytes) for A and B tiles
#define ATILE_BYTES 14336    // A buffer: 128x112 fp16 (single-rounded)
#define BTILE_BYTES 28672    // B buffer: 256x112 fp16

// smem layout (bytes): A double buffer, then B double buffer
#define SA_OFF 0
#define SB_OFF (2 * ATILE_BYTES)                       // 28672
#define SMEM_BYTES (SB_OFF + 2 * BTILE_BYTES)          // 86016

// ---------------- scratch (no cudaMalloc allowed) ----------------------------
__device__ __align__(16) __half g_Bt[NIT * 256 * BPITCH];  // pre-rounded fp16 W
__device__ __align__(16) float g_xT[NF * XP];             // x transposed [f][n]
__device__ __align__(16) float g_sp[(size_t)MAXN * NF];   // src projection
__device__ __align__(16) float g_dp[(size_t)MAXN * NF];   // dst projection
__device__ int g_cnt[MAXN];                               // per-dst degree
__device__ int g_cur[MAXN];                               // scatter cursors
__device__ int g_base[MAXN + 1];                          // bucket offsets
__device__ int g_blk[64];                                 // scan partials
__device__ int g_bucket[MAXE];                            // edge ids by dst
__device__ int g_is64;                                    // edge_index dtype flag

// ---------------- helpers -----------------------------------------------------
__device__ __forceinline__ uint32_t smem_u32(const void* p) {
    uint32_t a;
    asm("{ .reg .u64 t; cvta.to.shared.u64 t, %1; cvt.u32.u64 %0, t; }" : "=r"(a) : "l"(p));
    return a;
}
__device__ __forceinline__ void ldsm_x4(uint32_t addr, uint32_t* r) {
    asm volatile("ldmatrix.sync.aligned.m8n8.x4.shared.b16 {%0,%1,%2,%3}, [%4];"
                 : "=r"(r[0]), "=r"(r[1]), "=r"(r[2]), "=r"(r[3]) : "r"(addr));
}
__device__ __forceinline__ void mma_fp16(float* c, const uint32_t* a, uint32_t b0, uint32_t b1) {
    asm volatile("mma.sync.aligned.m16n8k16.row.col.f32.f16.f16.f32 "
                 "{%0,%1,%2,%3}, {%4,%5,%6,%7}, {%8,%9}, {%0,%1,%2,%3};"
                 : "+f"(c[0]), "+f"(c[1]), "+f"(c[2]), "+f"(c[3])
                 : "r"(a[0]), "r"(a[1]), "r"(a[2]), "r"(a[3]), "r"(b0), "r"(b1));
}
__device__ __forceinline__ long long get_idx(const void* ei, long long pos, int is64) {
    if (is64) return ((const long long*)ei)[pos];
    return (long long)((const int*)ei)[pos];
}

// ---------------- kernel 0: detect edge_index dtype ---------------------------
__global__ void detect_kernel(const int* __restrict__ ei_words, long long E) {
    if (blockIdx.x == 0 && threadIdx.x == 0) {
        int n = (int)(E < 512 ? E : 512);
        int nonzero = 0;
        for (int i = 0; i < n; i++) nonzero += (ei_words[2 * i + 1] != 0);
        g_is64 = (nonzero == 0) ? 1 : 0;
    }
}

// ---------------- kernel Z: zero degree counters -------------------------------
__global__ void zero_cnt_kernel(int N) {
    int i = blockIdx.x * blockDim.x + threadIdx.x;
    if (i < N) g_cnt[i] = 0;
}

// ---------------- kernel X: transpose x -> g_xT[f][n] -------------------------
__global__ void prep_xT_kernel(const float* __restrict__ x, int N) {
    __shared__ float t[32][33];
    int n0 = blockIdx.x * 32, f0 = blockIdx.y * 32;
    int tx = threadIdx.x, ty = threadIdx.y;
    for (int i = ty; i < 32; i += 8) {
        int n = n0 + i;
        t[i][tx] = (n < N) ? x[(size_t)n * NF + f0 + tx] : 0.0f;
    }
    __syncthreads();
    for (int i = ty; i < 32; i += 8)
        g_xT[(size_t)(f0 + i) * XP + n0 + tx] = t[tx][i];
}

// ---------------- kernel A: build pre-rounded fp16 weight tiles ---------------
__global__ void prep_wt_kernel(const float* __restrict__ bw_s, const float* __restrict__ sw_s,
                               const float* __restrict__ bw_d, const float* __restrict__ sw_d) {
    int idx = blockIdx.x * blockDim.x + threadIdx.x;
    if (idx >= NIT * 256 * BPITCH) return;
    int col  = idx % BPITCH;
    int n    = (idx / BPITCH) & 255;
    int it   = idx / (BPITCH * 256);
    float v = 0.0f;
    if (col < 48) {
        int f = it * 4 + col / 12;
        int c = col % 12;
        if (n < 128) v = (c < 11) ? sw_s[((size_t)n * NF + f) * 11 + c] : bw_s[(size_t)n * NF + f];
        else {
            int oo = n - 128;
            v = (c < 11) ? sw_d[((size_t)oo * NF + f) * 11 + c] : bw_d[(size_t)oo * NF + f];
        }
    }
    g_Bt[idx] = __float2half_rn(v);
}

// ---------------- binning: count / scan / scatter ------------------------------
__global__ void count_kernel(const void* __restrict__ ei, long long E) {
    const int is64 = g_is64;
    long long i = (long long)blockIdx.x * blockDim.x + threadIdx.x;
    if (i >= E) return;
    int d = (int)get_idx(ei, E + i, is64);
    atomicAdd(&g_cnt[d], 1);
}

__global__ void scanA_kernel(int N) {
    __shared__ int ss[1024];
    int tid = threadIdx.x;
    int i = blockIdx.x * 1024 + tid;
    int c = (i < N) ? g_cnt[i] : 0;
    ss[tid] = c;
    __syncthreads();
    for (int off = 1; off < 1024; off <<= 1) {
        int v = (tid >= off) ? ss[tid - off] : 0;
        __syncthreads();
        ss[tid] += v;
        __syncthreads();
    }
    if (i < N) g_base[i] = ss[tid] - c;           // exclusive within block
    if (tid == 1023) g_blk[blockIdx.x] = ss[1023];
}

__global__ void scanC_kernel(int N, int nb) {
    int tid = threadIdx.x;
    int i = blockIdx.x * 1024 + tid;
    int off = 0;
    for (int b = 0; b < blockIdx.x; b++) off += g_blk[b];
    if (i < N) { g_base[i] += off; g_cur[i] = 0; }
    if (blockIdx.x == 0 && tid == 0) {
        int t = 0;
        for (int b = 0; b < nb; b++) t += g_blk[b];
        g_base[N] = t;
    }
}

__global__ void scatter_kernel(const void* __restrict__ ei, long long E) {
    const int is64 = g_is64;
    long long i = (long long)blockIdx.x * blockDim.x + threadIdx.x;
    if (i >= E) return;
    int d = (int)get_idx(ei, E + i, is64);
    int pos = g_base[d] + atomicAdd(&g_cur[d], 1);
    g_bucket[pos] = (int)i;
}

// ---------------- act build: spline/silu values for (node r, feat f) ----------
// Single-rounded fp16 (no lo split).
__device__ __forceinline__ void store_h(uint32_t addr, float v) {
    uint16_t hb;
    asm("cvt.rn.f16.f32 %0, %1;" : "=h"(hb) : "f"(v));
    asm volatile("st.shared.b16 [%0], %1;" :: "r"(addr), "h"(hb));
}
__device__ __forceinline__ void build_act(uint32_t wbase, float xv) {
#pragma unroll
    for (int j = 0; j < 3; j++)
        asm volatile("st.shared.v2.b32 [%0], {%1, %1};" :: "r"(wbase + j * 8), "r"(0));
    float sil = xv / (1.0f + __expf(-xv));
    store_h(wbase + 22, sil);
    if (xv >= -1.75f && xv < 1.75f) {
        float t = fmaf(xv, 4.0f, 7.0f);
        int m = (int)t; if (m > 13) m = 13;
        float u = t - (float)m;
        float u1 = 1.0f - u;
        float uu = u * u;
        float w3 = uu * u * (1.0f / 6.0f);
        float w0 = u1 * u1 * u1 * (1.0f / 6.0f);
        float w1 = fmaf(uu, fmaf(u, 0.5f, -1.0f), 2.0f / 3.0f);   // (3u^3-6u^2+4)/6
        float w2 = 1.0f - w0 - w1 - w3;                           // partition of unity
        int c0 = m - 3;
        if (c0 >= 0 && c0 <= 10)         store_h(wbase + (c0    ) * 2, w0);
        if (c0 + 1 >= 0 && c0 + 1 <= 10) store_h(wbase + (c0 + 1) * 2, w1);
        if (c0 + 2 >= 0 && c0 + 2 <= 10) store_h(wbase + (c0 + 2) * 2, w2);
        if (c0 + 3 <= 10)                store_h(wbase + (c0 + 3) * 2, w3);
    }
}

// ---------------- kernel B: KAN projections, fp16 single-product --------------
// 256 threads / 8 warps; warp tile 64x64; CTA tile 128x256; K = 32 iters x 48.
__global__ __launch_bounds__(256, 1) void proj_gemm_kernel(int N) {
    extern __shared__ __align__(16) char smem[];
    const int tid  = threadIdx.x;
    const int lane = tid & 31;
    const int wid  = tid >> 5;
    const int wm   = wid >> 2;      // warp M index (0..1) -> 64 rows
    const int wn   = wid & 3;       // warp N index (0..3) -> 64 cols
    const int node0 = blockIdx.x * TILE_M;

    const uint32_t sb = smem_u32(smem);
    const uint32_t sA = sb + SA_OFF;
    const uint32_t sB = sb + SB_OFF;

    const int r = tid & 127;        // node row this thread builds
    const int q = tid >> 7;         // feature pair index (0..1); with k2 covers 0..3

    // ---- prologue: B tile 0 prefetch; acts for it=0 into A[0] ----
    const unsigned long long gB = (unsigned long long)__cvta_generic_to_global(g_Bt);
    for (int c = tid; c < BTILE_BYTES / 16; c += 256)
        asm volatile("cp.async.cg.shared.global [%0], [%1], 16;"
                     :: "r"(sB + c * 16), "l"(gB + (unsigned long long)c * 16));
    asm volatile("cp.async.commit_group;" ::: "memory");
#pragma unroll
    for (int k2 = 0; k2 < 2; k2++) {
        int qq = q + k2 * 2;
        float xv = g_xT[(size_t)qq * XP + node0 + r];
        build_act(sA + r * 112 + qq * 24, xv);
    }
    asm volatile("cp.async.wait_group 0;" ::: "memory");
    __syncthreads();

    float acc[32][4];
#pragma unroll
    for (int i = 0; i < 32; i++)
#pragma unroll
        for (int j = 0; j < 4; j++) acc[i][j] = 0.0f;

    // per-thread ldmatrix base offsets (within a buffer)
    const uint32_t aOff = (wm * 64 + (lane & 15)) * 112 + (lane >> 4) * 16;
    const uint32_t bOff = (wn * 64 + (lane & 7) + ((lane >> 4) << 3)) * 112 + ((lane >> 3) & 1) * 16;

    for (int it = 0; it < NIT; it++) {
        // ---- prefetch B(it+1) first, then build acts for it+1 ----
        if (it + 1 < NIT) {
            uint32_t bufNxt = sB + ((it + 1) & 1) * BTILE_BYTES;
            unsigned long long src = gB + (unsigned long long)(it + 1) * BTILE_BYTES;
            for (int c = tid; c < BTILE_BYTES / 16; c += 256)
                asm volatile("cp.async.cg.shared.global [%0], [%1], 16;"
                             :: "r"(bufNxt + c * 16), "l"(src + (unsigned long long)c * 16));
            asm volatile("cp.async.commit_group;" ::: "memory");
            uint32_t aNxt = sA + ((it + 1) & 1) * ATILE_BYTES;
#pragma unroll
            for (int k2 = 0; k2 < 2; k2++) {
                int qq = q + k2 * 2;
                float xv = g_xT[(size_t)((it + 1) * 4 + qq) * XP + node0 + r];
                build_act(aNxt + r * 112 + qq * 24, xv);
            }
        }

        // ---- MMA on iteration it: 3 K16 steps x 1 product ----
        const uint32_t aBase = sA + (it & 1) * ATILE_BYTES + aOff;
        const uint32_t bBase = sB + (it & 1) * BTILE_BYTES + bOff;
#pragma unroll 1
        for (int ks = 0; ks < 3; ks++) {
            uint32_t ah[4][4], bb[4][4];
#pragma unroll
            for (int mi = 0; mi < 4; mi++)
                ldsm_x4(aBase + mi * 1792 + ks * 32, ah[mi]);
#pragma unroll
            for (int nf2 = 0; nf2 < 4; nf2++) ldsm_x4(bBase + nf2 * 1792 + ks * 32, bb[nf2]);
#pragma unroll
            for (int mi = 0; mi < 4; mi++)
#pragma unroll
                for (int nf = 0; nf < 8; nf++)
                    mma_fp16(acc[mi * 8 + nf], ah[mi],
                             bb[nf >> 1][(nf & 1) * 2], bb[nf >> 1][(nf & 1) * 2 + 1]);
        }
        asm volatile("cp.async.wait_group 0;" ::: "memory");
        __syncthreads();
    }

    // ---- epilogue: write fragments (warp wn<2 -> g_sp, wn>=2 -> g_dp) ----
    float* dstbase = (wn < 2) ? g_sp : g_dp;
    const int colbase = (wn & 1) * 64 + (lane & 3) * 2;
#pragma unroll
    for (int mi = 0; mi < 4; mi++) {
        int node = node0 + wm * 64 + mi * 16 + (lane >> 2);
#pragma unroll
        for (int nf = 0; nf < 8; nf++) {
            int col = colbase + nf * 8;
            if (node < N)
                *(float2*)(dstbase + (size_t)node * NF + col)
                    = make_float2(acc[mi * 8 + nf][0], acc[mi * 8 + nf][1]);
            if (node + 8 < N)
                *(float2*)(dstbase + (size_t)(node + 8) * NF + col)
                    = make_float2(acc[mi * 8 + nf][2], acc[mi * 8 + nf][3]);
        }
    }
}

// ---------------- kernel E: fused attention + softmax + aggregation -----------
__global__ void fused_agg_kernel(const void* __restrict__ ei, long long E,
                                 const float* __restrict__ x, const float* __restrict__ da,
                                 const float* __restrict__ bias, const float* __restrict__ pa,
                                 float* __restrict__ outf, int N) {
    const int is64 = g_is64;
    int lane = threadIdx.x & 31;
    int node = blockIdx.x * 8 + (threadIdx.x >> 5);
    if (node >= N) return;
    int b0 = g_base[node], b1 = g_base[node + 1];

    float4 dpv = ((const float4*)(g_dp + (size_t)node * NF))[lane];
    float4 wav = ((const float4*)da)[lane];

    float den = 0.0f;
    float4 acc = make_float4(0.f, 0.f, 0.f, 0.f);
    for (int j = b0; j < b1; j++) {
        int e = g_bucket[j];
        long long s = get_idx(ei, e, is64);
        float4 v = ((const float4*)(g_sp + s * NF))[lane];
        float t0 = v.x + dpv.x; t0 = t0 >= 0.f ? t0 : 0.2f * t0;
        float t1 = v.y + dpv.y; t1 = t1 >= 0.f ? t1 : 0.2f * t1;
        float t2 = v.z + dpv.z; t2 = t2 >= 0.f ? t2 : 0.2f * t2;
        float t3 = v.w + dpv.w; t3 = t3 >= 0.f ? t3 : 0.2f * t3;
        float p = t0 * wav.x + t1 * wav.y + t2 * wav.z + t3 * wav.w;
        p += __shfl_xor_sync(0xffffffffu, p, 1);
        p += __shfl_xor_sync(0xffffffffu, p, 2);
        p += __shfl_xor_sync(0xffffffffu, p, 4);
        float ex = __expf(p);
        den += ex;
        acc.x += v.x * ex; acc.y += v.y * ex;
        acc.z += v.z * ex; acc.w += v.w * ex;
    }
    float inv = 1.0f / (den + 1e-16f);

    float4 xr = ((const float4*)(x + (size_t)node * NF))[lane];
    float4 bb = ((const float4*)bias)[lane];
    float a = pa[0];
    float4 o;
    o.x = acc.x * inv + xr.x + bb.x; o.x = o.x >= 0.f ? o.x : a * o.x;
    o.y = acc.y * inv + xr.y + bb.y; o.y = o.y >= 0.f ? o.y : a * o.y;
    o.z = acc.z * inv + xr.z + bb.z; o.z = o.z >= 0.f ? o.z : a * o.z;
    o.w = acc.w * inv + xr.w + bb.w; o.w = o.w >= 0.f ? o.w : a * o.w;
    ((float4*)(outf + (size_t)node * NF))[lane] = o;
}

// ---------------- launch -------------------------------------------------------
extern "C" void kernel_launch(void* const* d_in, const int* in_sizes, int n_in,
                              void* d_out, int out_size) {
    const float* x    = (const float*)d_in[0];
    const void*  ei   = d_in[1];
    const float* bw_s = (const float*)d_in[2];
    const float* sw_s = (const float*)d_in[3];
    const float* bw_d = (const float*)d_in[4];
    const float* sw_d = (const float*)d_in[5];
    const float* da   = (const float*)d_in[6];
    const float* bias = (const float*)d_in[7];
    const float* pa   = (const float*)d_in[8];
    float* outf = (float*)d_out;

    int       N = in_sizes[0] / NF;
    long long E = (long long)in_sizes[1] / 2;
    int nb = (N + 1023) / 1024;

    cudaFuncSetAttribute(proj_gemm_kernel, cudaFuncAttributeMaxDynamicSharedMemorySize, SMEM_BYTES);

    detect_kernel<<<1, 32>>>((const int*)ei, E);
    zero_cnt_kernel<<<(N + 255) / 256, 256>>>(N);
    prep_xT_kernel<<<dim3((N + 31) / 32, 4), dim3(32, 8)>>>(x, N);
    prep_wt_kernel<<<(NIT * 256 * BPITCH + 255) / 256, 256>>>(bw_s, sw_s, bw_d, sw_d);
    count_kernel<<<(int)((E + 255) / 256), 256>>>(ei, E);
    scanA_kernel<<<nb, 1024>>>(N);
    scanC_kernel<<<nb, 1024>>>(N, nb);
    scatter_kernel<<<(int)((E + 255) / 256), 256>>>(ei, E);
    proj_gemm_kernel<<<(N + TILE_M - 1) / TILE_M, 256, SMEM_BYTES>>>(N);
    fused_agg_kernel<<<(N + 7) / 8, 256>>>(ei, E, x, da, bias, pa, outf, N);
}

// round 16
// speedup vs baseline: 1.6289x; 1.6289x over previous
#include <cuda_runtime.h>
#include <cuda_fp16.h>
#include <cstdint>

// ---------------- problem constants -----------------------------------------
#define NF     128           // node features == H*D
#define MAXN   50000
#define XP     50176         // g_xT pitch (nodes, padded)
#define MAXE   800000
#define TILE_M 128           // nodes per CTA
#define NIT    32            // K iterations (128 features / 4 per iter)
#define BPITCH 56            // fp16 col pitch (112 bytes) for A and B tiles
#define ATILE_BYTES 14336    // A buffer: 128x112 fp16 (single-rounded)
#define BTILE_BYTES 28672    // B buffer: 256x112 fp16

// smem layout (bytes): A double buffer, then B double buffer
#define SA_OFF 0
#define SB_OFF (2 * ATILE_BYTES)                       // 28672
#define SMEM_BYTES (SB_OFF + 2 * BTILE_BYTES)          // 86016

// ---------------- scratch (no cudaMalloc allowed) ----------------------------
__device__ __align__(16) __half g_Bt[NIT * 256 * BPITCH];  // pre-rounded fp16 W
__device__ __align__(16) float g_xT[NF * XP];             // x transposed [f][n]
__device__ __align__(16) float g_sp[(size_t)MAXN * NF];   // src projection
__device__ __align__(16) float g_dp[(size_t)MAXN * NF];   // dst projection
__device__ int g_cnt[MAXN];                               // per-dst degree
__device__ int g_cur[MAXN];                               // scatter cursors
__device__ int g_base[MAXN + 1];                          // bucket offsets
__device__ int g_blk[64];                                 // scan partials
__device__ int g_bucket[MAXE];                            // edge ids by dst
__device__ int g_is64;                                    // edge_index dtype flag

// ---------------- helpers -----------------------------------------------------
__device__ __forceinline__ uint32_t smem_u32(const void* p) {
    uint32_t a;
    asm("{ .reg .u64 t; cvta.to.shared.u64 t, %1; cvt.u32.u64 %0, t; }" : "=r"(a) : "l"(p));
    return a;
}
__device__ __forceinline__ void ldsm_x4(uint32_t addr, uint32_t* r) {
    asm volatile("ldmatrix.sync.aligned.m8n8.x4.shared.b16 {%0,%1,%2,%3}, [%4];"
                 : "=r"(r[0]), "=r"(r[1]), "=r"(r[2]), "=r"(r[3]) : "r"(addr));
}
__device__ __forceinline__ void mma_fp16(float* c, const uint32_t* a, uint32_t b0, uint32_t b1) {
    asm volatile("mma.sync.aligned.m16n8k16.row.col.f32.f16.f16.f32 "
                 "{%0,%1,%2,%3}, {%4,%5,%6,%7}, {%8,%9}, {%0,%1,%2,%3};"
                 : "+f"(c[0]), "+f"(c[1]), "+f"(c[2]), "+f"(c[3])
                 : "r"(a[0]), "r"(a[1]), "r"(a[2]), "r"(a[3]), "r"(b0), "r"(b1));
}
__device__ __forceinline__ long long get_idx(const void* ei, long long pos, int is64) {
    if (is64) return ((const long long*)ei)[pos];
    return (long long)((const int*)ei)[pos];
}

// ---------------- kernel 0: detect edge_index dtype ---------------------------
__global__ void detect_kernel(const int* __restrict__ ei_words, long long E) {
    if (blockIdx.x == 0 && threadIdx.x == 0) {
        int n = (int)(E < 512 ? E : 512);
        int nonzero = 0;
        for (int i = 0; i < n; i++) nonzero += (ei_words[2 * i + 1] != 0);
        g_is64 = (nonzero == 0) ? 1 : 0;
    }
}

// ---------------- kernel Z: zero degree counters -------------------------------
__global__ void zero_cnt_kernel(int N) {
    int i = blockIdx.x * blockDim.x + threadIdx.x;
    if (i < N) g_cnt[i] = 0;
}

// ---------------- kernel X: transpose x -> g_xT[f][n] -------------------------
__global__ void prep_xT_kernel(const float* __restrict__ x, int N) {
    __shared__ float t[32][33];
    int n0 = blockIdx.x * 32, f0 = blockIdx.y * 32;
    int tx = threadIdx.x, ty = threadIdx.y;
    for (int i = ty; i < 32; i += 8) {
        int n = n0 + i;
        t[i][tx] = (n < N) ? x[(size_t)n * NF + f0 + tx] : 0.0f;
    }
    __syncthreads();
    for (int i = ty; i < 32; i += 8)
        g_xT[(size_t)(f0 + i) * XP + n0 + tx] = t[tx][i];
}

// ---------------- kernel A: build pre-rounded fp16 weight tiles ---------------
__global__ void prep_wt_kernel(const float* __restrict__ bw_s, const float* __restrict__ sw_s,
                               const float* __restrict__ bw_d, const float* __restrict__ sw_d) {
    int idx = blockIdx.x * blockDim.x + threadIdx.x;
    if (idx >= NIT * 256 * BPITCH) return;
    int col  = idx % BPITCH;
    int n    = (idx / BPITCH) & 255;
    int it   = idx / (BPITCH * 256);
    float v = 0.0f;
    if (col < 48) {
        int f = it * 4 + col / 12;
        int c = col % 12;
        if (n < 128) v = (c < 11) ? sw_s[((size_t)n * NF + f) * 11 + c] : bw_s[(size_t)n * NF + f];
        else {
            int oo = n - 128;
            v = (c < 11) ? sw_d[((size_t)oo * NF + f) * 11 + c] : bw_d[(size_t)oo * NF + f];
        }
    }
    g_Bt[idx] = __float2half_rn(v);
}

// ---------------- binning: count / scan / scatter ------------------------------
__global__ void count_kernel(const void* __restrict__ ei, long long E) {
    const int is64 = g_is64;
    long long i = (long long)blockIdx.x * blockDim.x + threadIdx.x;
    if (i >= E) return;
    int d = (int)get_idx(ei, E + i, is64);
    atomicAdd(&g_cnt[d], 1);
}

__global__ void scanA_kernel(int N) {
    __shared__ int ss[1024];
    int tid = threadIdx.x;
    int i = blockIdx.x * 1024 + tid;
    int c = (i < N) ? g_cnt[i] : 0;
    ss[tid] = c;
    __syncthreads();
    for (int off = 1; off < 1024; off <<= 1) {
        int v = (tid >= off) ? ss[tid - off] : 0;
        __syncthreads();
        ss[tid] += v;
        __syncthreads();
    }
    if (i < N) g_base[i] = ss[tid] - c;           // exclusive within block
    if (tid == 1023) g_blk[blockIdx.x] = ss[1023];
}

__global__ void scanC_kernel(int N, int nb) {
    int tid = threadIdx.x;
    int i = blockIdx.x * 1024 + tid;
    int off = 0;
    for (int b = 0; b < blockIdx.x; b++) off += g_blk[b];
    if (i < N) { g_base[i] += off; g_cur[i] = 0; }
    if (blockIdx.x == 0 && tid == 0) {
        int t = 0;
        for (int b = 0; b < nb; b++) t += g_blk[b];
        g_base[N] = t;
    }
}

__global__ void scatter_kernel(const void* __restrict__ ei, long long E) {
    const int is64 = g_is64;
    long long i = (long long)blockIdx.x * blockDim.x + threadIdx.x;
    if (i >= E) return;
    int d = (int)get_idx(ei, E + i, is64);
    int pos = g_base[d] + atomicAdd(&g_cur[d], 1);
    g_bucket[pos] = (int)i;
}

// ---------------- act build: spline/silu values for (node r, feat f) ----------
__device__ __forceinline__ void store_h(uint32_t addr, float v) {
    uint16_t hb;
    asm("cvt.rn.f16.f32 %0, %1;" : "=h"(hb) : "f"(v));
    asm volatile("st.shared.b16 [%0], %1;" :: "r"(addr), "h"(hb));
}
__device__ __forceinline__ void build_act(uint32_t wbase, float xv) {
#pragma unroll
    for (int j = 0; j < 3; j++)
        asm volatile("st.shared.v2.b32 [%0], {%1, %1};" :: "r"(wbase + j * 8), "r"(0));
    float sil = xv / (1.0f + __expf(-xv));
    store_h(wbase + 22, sil);
    if (xv >= -1.75f && xv < 1.75f) {
        float t = fmaf(xv, 4.0f, 7.0f);
        int m = (int)t; if (m > 13) m = 13;
        float u = t - (float)m;
        float u1 = 1.0f - u;
        float uu = u * u;
        float w3 = uu * u * (1.0f / 6.0f);
        float w0 = u1 * u1 * u1 * (1.0f / 6.0f);
        float w1 = fmaf(uu, fmaf(u, 0.5f, -1.0f), 2.0f / 3.0f);   // (3u^3-6u^2+4)/6
        float w2 = 1.0f - w0 - w1 - w3;                           // partition of unity
        int c0 = m - 3;
        if (c0 >= 0 && c0 <= 10)         store_h(wbase + (c0    ) * 2, w0);
        if (c0 + 1 >= 0 && c0 + 1 <= 10) store_h(wbase + (c0 + 1) * 2, w1);
        if (c0 + 2 >= 0 && c0 + 2 <= 10) store_h(wbase + (c0 + 2) * 2, w2);
        if (c0 + 3 <= 10)                store_h(wbase + (c0 + 3) * 2, w3);
    }
}

// ---------------- kernel B: KAN projections, fp16 single-product --------------
// 512 threads / 16 warps; warp tile 64x32; CTA tile 128x256; K = 32 iters x 48.
// ~113 regs/thread fits the 128-reg cap; 4 warps/SMSP hides HMMA/ldsm latency.
__global__ __launch_bounds__(512, 1) void proj_gemm_kernel(int N) {
    extern __shared__ __align__(16) char smem[];
    const int tid  = threadIdx.x;
    const int lane = tid & 31;
    const int wid  = tid >> 5;
    const int wm   = wid >> 3;      // 0..1 -> 64-row band
    const int wn   = wid & 7;       // 0..7 -> 32-col band
    const int node0 = blockIdx.x * TILE_M;

    const uint32_t sb = smem_u32(smem);
    const uint32_t sA = sb + SA_OFF;
    const uint32_t sB = sb + SB_OFF;

    const int r = tid & 127;        // node row this thread builds
    const int q = tid >> 7;         // feature index (0..3)

    // ---- prologue: B tile 0 prefetch; acts for it=0 into A[0] ----
    const unsigned long long gB = (unsigned long long)__cvta_generic_to_global(g_Bt);
    for (int c = tid; c < BTILE_BYTES / 16; c += 512)
        asm volatile("cp.async.cg.shared.global [%0], [%1], 16;"
                     :: "r"(sB + c * 16), "l"(gB + (unsigned long long)c * 16));
    asm volatile("cp.async.commit_group;" ::: "memory");
    {
        float xv = g_xT[(size_t)q * XP + node0 + r];
        build_act(sA + r * 112 + q * 24, xv);
    }
    asm volatile("cp.async.wait_group 0;" ::: "memory");
    __syncthreads();

    float acc[16][4];
#pragma unroll
    for (int i = 0; i < 16; i++)
#pragma unroll
        for (int j = 0; j < 4; j++) acc[i][j] = 0.0f;

    // per-thread ldmatrix base offsets (within a buffer)
    const uint32_t aOff = (wm * 64 + (lane & 15)) * 112 + (lane >> 4) * 16;
    const uint32_t bOff = (wn * 32 + (lane & 7) + ((lane >> 4) << 3)) * 112 + ((lane >> 3) & 1) * 16;

    for (int it = 0; it < NIT; it++) {
        // ---- prefetch B(it+1) first, then build act for it+1 ----
        if (it + 1 < NIT) {
            uint32_t bufNxt = sB + ((it + 1) & 1) * BTILE_BYTES;
            unsigned long long src = gB + (unsigned long long)(it + 1) * BTILE_BYTES;
            for (int c = tid; c < BTILE_BYTES / 16; c += 512)
                asm volatile("cp.async.cg.shared.global [%0], [%1], 16;"
                             :: "r"(bufNxt + c * 16), "l"(src + (unsigned long long)c * 16));
            asm volatile("cp.async.commit_group;" ::: "memory");
            uint32_t aNxt = sA + ((it + 1) & 1) * ATILE_BYTES;
            float xv = g_xT[(size_t)((it + 1) * 4 + q) * XP + node0 + r];
            build_act(aNxt + r * 112 + q * 24, xv);
        }

        // ---- MMA on iteration it: 3 K16 steps x 1 product (warp tile 64x32) --
        const uint32_t aBase = sA + (it & 1) * ATILE_BYTES + aOff;
        const uint32_t bBase = sB + (it & 1) * BTILE_BYTES + bOff;
#pragma unroll 1
        for (int ks = 0; ks < 3; ks++) {
            uint32_t ah[4][4], bb[2][4];
#pragma unroll
            for (int mi = 0; mi < 4; mi++)
                ldsm_x4(aBase + mi * 1792 + ks * 32, ah[mi]);
#pragma unroll
            for (int n2 = 0; n2 < 2; n2++)
                ldsm_x4(bBase + n2 * 1792 + ks * 32, bb[n2]);
#pragma unroll
            for (int mi = 0; mi < 4; mi++)
#pragma unroll
                for (int nf = 0; nf < 4; nf++)
                    mma_fp16(acc[mi * 4 + nf], ah[mi],
                             bb[nf >> 1][(nf & 1) * 2], bb[nf >> 1][(nf & 1) * 2 + 1]);
        }
        asm volatile("cp.async.wait_group 0;" ::: "memory");
        __syncthreads();
    }

    // ---- epilogue: warp (wm,wn): wn<4 -> g_sp, wn>=4 -> g_dp ----
    float* dstbase = (wn < 4) ? g_sp : g_dp;
    const int colbase = (wn & 3) * 32 + (lane & 3) * 2;
#pragma unroll
    for (int mi = 0; mi < 4; mi++) {
        int node = node0 + wm * 64 + mi * 16 + (lane >> 2);
#pragma unroll
        for (int nf = 0; nf < 4; nf++) {
            int col = colbase + nf * 8;
            if (node < N)
                *(float2*)(dstbase + (size_t)node * NF + col)
                    = make_float2(acc[mi * 4 + nf][0], acc[mi * 4 + nf][1]);
            if (node + 8 < N)
                *(float2*)(dstbase + (size_t)(node + 8) * NF + col)
                    = make_float2(acc[mi * 4 + nf][2], acc[mi * 4 + nf][3]);
        }
    }
}

// ---------------- kernel E: fused attention + softmax + aggregation -----------
__global__ void fused_agg_kernel(const void* __restrict__ ei, long long E,
                                 const float* __restrict__ x, const float* __restrict__ da,
                                 const float* __restrict__ bias, const float* __restrict__ pa,
                                 float* __restrict__ outf, int N) {
    const int is64 = g_is64;
    int lane = threadIdx.x & 31;
    int node = blockIdx.x * 8 + (threadIdx.x >> 5);
    if (node >= N) return;
    int b0 = g_base[node], b1 = g_base[node + 1];

    float4 dpv = ((const float4*)(g_dp + (size_t)node * NF))[lane];
    float4 wav = ((const float4*)da)[lane];

    float den = 0.0f;
    float4 acc = make_float4(0.f, 0.f, 0.f, 0.f);
    for (int j = b0; j < b1; j++) {
        int e = g_bucket[j];
        long long s = get_idx(ei, e, is64);
        float4 v = ((const float4*)(g_sp + s * NF))[lane];
        float t0 = v.x + dpv.x; t0 = t0 >= 0.f ? t0 : 0.2f * t0;
        float t1 = v.y + dpv.y; t1 = t1 >= 0.f ? t1 : 0.2f * t1;
        float t2 = v.z + dpv.z; t2 = t2 >= 0.f ? t2 : 0.2f * t2;
        float t3 = v.w + dpv.w; t3 = t3 >= 0.f ? t3 : 0.2f * t3;
        float p = t0 * wav.x + t1 * wav.y + t2 * wav.z + t3 * wav.w;
        p += __shfl_xor_sync(0xffffffffu, p, 1);
        p += __shfl_xor_sync(0xffffffffu, p, 2);
        p += __shfl_xor_sync(0xffffffffu, p, 4);
        float ex = __expf(p);
        den += ex;
        acc.x += v.x * ex; acc.y += v.y * ex;
        acc.z += v.z * ex; acc.w += v.w * ex;
    }
    float inv = 1.0f / (den + 1e-16f);

    float4 xr = ((const float4*)(x + (size_t)node * NF))[lane];
    float4 bb = ((const float4*)bias)[lane];
    float a = pa[0];
    float4 o;
    o.x = acc.x * inv + xr.x + bb.x; o.x = o.x >= 0.f ? o.x : a * o.x;
    o.y = acc.y * inv + xr.y + bb.y; o.y = o.y >= 0.f ? o.y : a * o.y;
    o.z = acc.z * inv + xr.z + bb.z; o.z = o.z >= 0.f ? o.z : a * o.z;
    o.w = acc.w * inv + xr.w + bb.w; o.w = o.w >= 0.f ? o.w : a * o.w;
    ((float4*)(outf + (size_t)node * NF))[lane] = o;
}

// ---------------- launch -------------------------------------------------------
extern "C" void kernel_launch(void* const* d_in, const int* in_sizes, int n_in,
                              void* d_out, int out_size) {
    const float* x    = (const float*)d_in[0];
    const void*  ei   = d_in[1];
    const float* bw_s = (const float*)d_in[2];
    const float* sw_s = (const float*)d_in[3];
    const float* bw_d = (const float*)d_in[4];
    const float* sw_d = (const float*)d_in[5];
    const float* da   = (const float*)d_in[6];
    const float* bias = (const float*)d_in[7];
    const float* pa   = (const float*)d_in[8];
    float* outf = (float*)d_out;

    int       N = in_sizes[0] / NF;
    long long E = (long long)in_sizes[1] / 2;
    int nb = (N + 1023) / 1024;

    cudaFuncSetAttribute(proj_gemm_kernel, cudaFuncAttributeMaxDynamicSharedMemorySize, SMEM_BYTES);

    detect_kernel<<<1, 32>>>((const int*)ei, E);
    zero_cnt_kernel<<<(N + 255) / 256, 256>>>(N);
    prep_xT_kernel<<<dim3((N + 31) / 32, 4), dim3(32, 8)>>>(x, N);
    prep_wt_kernel<<<(NIT * 256 * BPITCH + 255) / 256, 256>>>(bw_s, sw_s, bw_d, sw_d);
    count_kernel<<<(int)((E + 255) / 256), 256>>>(ei, E);
    scanA_kernel<<<nb, 1024>>>(N);
    scanC_kernel<<<nb, 1024>>>(N, nb);
    scatter_kernel<<<(int)((E + 255) / 256), 256>>>(ei, E);
    proj_gemm_kernel<<<(N + TILE_M - 1) / TILE_M, 512, SMEM_BYTES>>>(N);
    fused_agg_kernel<<<(N + 7) / 8, 256>>>(ei, E, x, da, bias, pa, outf, N);
}

// round 17
// speedup vs baseline: 1.8099x; 1.1111x over previous
#include <cuda_runtime.h>
#include <cuda_fp16.h>
#include <cstdint>

// ---------------- problem constants -----------------------------------------
#define NF     128           // node features == H*D
#define MAXN   50000
#define XP     50176         // g_xT pitch (nodes, padded)
#define MAXE   800000
#define TILE_M 128           // nodes per CTA
#define NIT    16            // K iterations (128 features / 8 per iter)
#define BPCOL  120           // B/A col pitch in halfs (240 bytes), 96 used
#define APITCH 240           // bytes per row
#define ATILE_BYTES (128 * APITCH)   // 30720
#define BTILE_BYTES (256 * APITCH)   // 61440

// smem layout (bytes): A double buffer, then B double buffer
#define SA_OFF 0
#define SB_OFF (2 * ATILE_BYTES)                       // 61440
#define SMEM_BYTES (SB_OFF + 2 * BTILE_BYTES)          // 184320

// ---------------- scratch (no cudaMalloc allowed) ----------------------------
__device__ __align__(16) __half g_Bt[NIT * 256 * BPCOL];  // pre-rounded fp16 W
__device__ __align__(16) float g_xT[NF * XP];             // x transposed [f][n]
__device__ __align__(16) float g_sp[(size_t)MAXN * NF];   // src projection
__device__ __align__(16) float g_dp[(size_t)MAXN * NF];   // dst projection
__device__ int g_cnt[MAXN];                               // per-dst degree (zero-init)
__device__ int g_cur[MAXN];                               // scatter cursors
__device__ int g_base[MAXN + 1];                          // bucket offsets
__device__ int g_blk[64];                                 // scan partials
__device__ int g_bucket[MAXE];                            // edge ids by dst
__device__ int g_is64;                                    // edge_index dtype flag

// ---------------- helpers -----------------------------------------------------
__device__ __forceinline__ uint32_t smem_u32(const void* p) {
    uint32_t a;
    asm("{ .reg .u64 t; cvta.to.shared.u64 t, %1; cvt.u32.u64 %0, t; }" : "=r"(a) : "l"(p));
    return a;
}
__device__ __forceinline__ void ldsm_x4(uint32_t addr, uint32_t* r) {
    asm volatile("ldmatrix.sync.aligned.m8n8.x4.shared.b16 {%0,%1,%2,%3}, [%4];"
                 : "=r"(r[0]), "=r"(r[1]), "=r"(r[2]), "=r"(r[3]) : "r"(addr));
}
__device__ __forceinline__ void mma_fp16(float* c, const uint32_t* a, uint32_t b0, uint32_t b1) {
    asm volatile("mma.sync.aligned.m16n8k16.row.col.f32.f16.f16.f32 "
                 "{%0,%1,%2,%3}, {%4,%5,%6,%7}, {%8,%9}, {%0,%1,%2,%3};"
                 : "+f"(c[0]), "+f"(c[1]), "+f"(c[2]), "+f"(c[3])
                 : "r"(a[0]), "r"(a[1]), "r"(a[2]), "r"(a[3]), "r"(b0), "r"(b1));
}
__device__ __forceinline__ long long get_idx(const void* ei, long long pos, int is64) {
    if (is64) return ((const long long*)ei)[pos];
    return (long long)((const int*)ei)[pos];
}

// ---------------- kernel 0: detect edge_index dtype ---------------------------
__global__ void detect_kernel(const int* __restrict__ ei_words, long long E) {
    if (blockIdx.x == 0 && threadIdx.x == 0) {
        int n = (int)(E < 512 ? E : 512);
        int nonzero = 0;
        for (int i = 0; i < n; i++) nonzero += (ei_words[2 * i + 1] != 0);
        g_is64 = (nonzero == 0) ? 1 : 0;
    }
}

// ---------------- kernel X: transpose x -> g_xT[f][n] -------------------------
__global__ void prep_xT_kernel(const float* __restrict__ x, int N) {
    __shared__ float t[32][33];
    int n0 = blockIdx.x * 32, f0 = blockIdx.y * 32;
    int tx = threadIdx.x, ty = threadIdx.y;
    for (int i = ty; i < 32; i += 8) {
        int n = n0 + i;
        t[i][tx] = (n < N) ? x[(size_t)n * NF + f0 + tx] : 0.0f;
    }
    __syncthreads();
    for (int i = ty; i < 32; i += 8)
        g_xT[(size_t)(f0 + i) * XP + n0 + tx] = t[tx][i];
}

// ---------------- kernel A: build pre-rounded fp16 weight tiles ---------------
// Per iter image: 256 rows x 120 halfs (240B); cols 0..95 = 8 feats x 12.
__global__ void prep_wt_kernel(const float* __restrict__ bw_s, const float* __restrict__ sw_s,
                               const float* __restrict__ bw_d, const float* __restrict__ sw_d) {
    int idx = blockIdx.x * blockDim.x + threadIdx.x;
    if (idx >= NIT * 256 * BPCOL) return;
    int col  = idx % BPCOL;
    int n    = (idx / BPCOL) & 255;
    int it   = idx / (BPCOL * 256);
    float v = 0.0f;
    if (col < 96) {
        int f = it * 8 + col / 12;
        int c = col % 12;
        if (n < 128) v = (c < 11) ? sw_s[((size_t)n * NF + f) * 11 + c] : bw_s[(size_t)n * NF + f];
        else {
            int oo = n - 128;
            v = (c < 11) ? sw_d[((size_t)oo * NF + f) * 11 + c] : bw_d[(size_t)oo * NF + f];
        }
    }
    g_Bt[idx] = __float2half_rn(v);
}

// ---------------- binning: count / scan / scatter ------------------------------
__global__ void count_kernel(const void* __restrict__ ei, long long E) {
    const int is64 = g_is64;
    long long i = (long long)blockIdx.x * blockDim.x + threadIdx.x;
    if (i >= E) return;
    int d = (int)get_idx(ei, E + i, is64);
    atomicAdd(&g_cnt[d], 1);
}

__global__ void scanA_kernel(int N) {
    __shared__ int ss[1024];
    int tid = threadIdx.x;
    int i = blockIdx.x * 1024 + tid;
    int c = (i < N) ? g_cnt[i] : 0;
    ss[tid] = c;
    __syncthreads();
    for (int off = 1; off < 1024; off <<= 1) {
        int v = (tid >= off) ? ss[tid - off] : 0;
        __syncthreads();
        ss[tid] += v;
        __syncthreads();
    }
    if (i < N) g_base[i] = ss[tid] - c;           // exclusive within block
    if (tid == 1023) g_blk[blockIdx.x] = ss[1023];
}

// also re-zeroes g_cnt for the next graph replay (first run: static zero-init)
__global__ void scanC_kernel(int N, int nb) {
    int tid = threadIdx.x;
    int i = blockIdx.x * 1024 + tid;
    int off = 0;
    for (int b = 0; b < blockIdx.x; b++) off += g_blk[b];
    if (i < N) { g_base[i] += off; g_cur[i] = 0; g_cnt[i] = 0; }
    if (blockIdx.x == 0 && tid == 0) {
        int t = 0;
        for (int b = 0; b < nb; b++) t += g_blk[b];
        g_base[N] = t;
    }
}

__global__ void scatter_kernel(const void* __restrict__ ei, long long E) {
    const int is64 = g_is64;
    long long i = (long long)blockIdx.x * blockDim.x + threadIdx.x;
    if (i >= E) return;
    int d = (int)get_idx(ei, E + i, is64);
    int pos = g_base[d] + atomicAdd(&g_cur[d], 1);
    g_bucket[pos] = (int)i;
}

// ---------------- act build: spline/silu values for (node r, feat f) ----------
__device__ __forceinline__ void store_h(uint32_t addr, float v) {
    uint16_t hb;
    asm("cvt.rn.f16.f32 %0, %1;" : "=h"(hb) : "f"(v));
    asm volatile("st.shared.b16 [%0], %1;" :: "r"(addr), "h"(hb));
}
__device__ __forceinline__ void build_act(uint32_t wbase, float xv) {
#pragma unroll
    for (int j = 0; j < 3; j++)
        asm volatile("st.shared.v2.b32 [%0], {%1, %1};" :: "r"(wbase + j * 8), "r"(0));
    float sil = xv / (1.0f + __expf(-xv));
    store_h(wbase + 22, sil);
    if (xv >= -1.75f && xv < 1.75f) {
        float t = fmaf(xv, 4.0f, 7.0f);
        int m = (int)t; if (m > 13) m = 13;
        float u = t - (float)m;
        float u1 = 1.0f - u;
        float uu = u * u;
        float w3 = uu * u * (1.0f / 6.0f);
        float w0 = u1 * u1 * u1 * (1.0f / 6.0f);
        float w1 = fmaf(uu, fmaf(u, 0.5f, -1.0f), 2.0f / 3.0f);   // (3u^3-6u^2+4)/6
        float w2 = 1.0f - w0 - w1 - w3;                           // partition of unity
        int c0 = m - 3;
        if (c0 >= 0 && c0 <= 10)         store_h(wbase + (c0    ) * 2, w0);
        if (c0 + 1 >= 0 && c0 + 1 <= 10) store_h(wbase + (c0 + 1) * 2, w1);
        if (c0 + 2 >= 0 && c0 + 2 <= 10) store_h(wbase + (c0 + 2) * 2, w2);
        if (c0 + 3 <= 10)                store_h(wbase + (c0 + 3) * 2, w3);
    }
}

// ---------------- kernel B: KAN projections, fp16 single-product --------------
// 512 threads / 16 warps; warp tile 64x32; CTA tile 128x256; K = 16 iters x 96.
__global__ __launch_bounds__(512, 1) void proj_gemm_kernel(int N) {
    extern __shared__ __align__(16) char smem[];
    const int tid  = threadIdx.x;
    const int lane = tid & 31;
    const int wid  = tid >> 5;
    const int wm   = wid >> 3;      // 0..1 -> 64-row band
    const int wn   = wid & 7;       // 0..7 -> 32-col band
    const int node0 = blockIdx.x * TILE_M;

    const uint32_t sb = smem_u32(smem);
    const uint32_t sA = sb + SA_OFF;
    const uint32_t sB = sb + SB_OFF;

    const int r = tid & 127;        // node row this thread builds
    const int q = tid >> 7;         // feature index base (0..3); +4 via k2

    // ---- prologue: B tile 0 prefetch; acts for it=0 into A[0] ----
    const unsigned long long gB = (unsigned long long)__cvta_generic_to_global(g_Bt);
    for (int c = tid; c < BTILE_BYTES / 16; c += 512)
        asm volatile("cp.async.cg.shared.global [%0], [%1], 16;"
                     :: "r"(sB + c * 16), "l"(gB + (unsigned long long)c * 16));
    asm volatile("cp.async.commit_group;" ::: "memory");
#pragma unroll
    for (int k2 = 0; k2 < 2; k2++) {
        int qq = q + k2 * 4;
        float xv = g_xT[(size_t)qq * XP + node0 + r];
        build_act(sA + r * APITCH + qq * 24, xv);
    }
    asm volatile("cp.async.wait_group 0;" ::: "memory");
    __syncthreads();

    float acc[16][4];
#pragma unroll
    for (int i = 0; i < 16; i++)
#pragma unroll
        for (int j = 0; j < 4; j++) acc[i][j] = 0.0f;

    // per-thread ldmatrix base offsets (within a buffer)
    const uint32_t aOff = (wm * 64 + (lane & 15)) * APITCH + (lane >> 4) * 16;
    const uint32_t bOff = (wn * 32 + (lane & 7) + ((lane >> 4) << 3)) * APITCH + ((lane >> 3) & 1) * 16;

    for (int it = 0; it < NIT; it++) {
        // ---- prefetch B(it+1) first, then build acts for it+1 ----
        if (it + 1 < NIT) {
            uint32_t bufNxt = sB + ((it + 1) & 1) * BTILE_BYTES;
            unsigned long long src = gB + (unsigned long long)(it + 1) * BTILE_BYTES;
            for (int c = tid; c < BTILE_BYTES / 16; c += 512)
                asm volatile("cp.async.cg.shared.global [%0], [%1], 16;"
                             :: "r"(bufNxt + c * 16), "l"(src + (unsigned long long)c * 16));
            asm volatile("cp.async.commit_group;" ::: "memory");
            uint32_t aNxt = sA + ((it + 1) & 1) * ATILE_BYTES;
#pragma unroll
            for (int k2 = 0; k2 < 2; k2++) {
                int qq = q + k2 * 4;
                float xv = g_xT[(size_t)((it + 1) * 8 + qq) * XP + node0 + r];
                build_act(aNxt + r * APITCH + qq * 24, xv);
            }
        }

        // ---- MMA on iteration it: 6 K16 steps x 1 product (warp tile 64x32) --
        const uint32_t aBase = sA + (it & 1) * ATILE_BYTES + aOff;
        const uint32_t bBase = sB + (it & 1) * BTILE_BYTES + bOff;
#pragma unroll 1
        for (int ks = 0; ks < 6; ks++) {
            uint32_t ah[4][4], bb[2][4];
#pragma unroll
            for (int mi = 0; mi < 4; mi++)
                ldsm_x4(aBase + mi * (16 * APITCH) + ks * 32, ah[mi]);
#pragma unroll
            for (int n2 = 0; n2 < 2; n2++)
                ldsm_x4(bBase + n2 * (16 * APITCH) + ks * 32, bb[n2]);
#pragma unroll
            for (int mi = 0; mi < 4; mi++)
#pragma unroll
                for (int nf = 0; nf < 4; nf++)
                    mma_fp16(acc[mi * 4 + nf], ah[mi],
                             bb[nf >> 1][(nf & 1) * 2], bb[nf >> 1][(nf & 1) * 2 + 1]);
        }
        asm volatile("cp.async.wait_group 0;" ::: "memory");
        __syncthreads();
    }

    // ---- epilogue: warp (wm,wn): wn<4 -> g_sp, wn>=4 -> g_dp ----
    float* dstbase = (wn < 4) ? g_sp : g_dp;
    const int colbase = (wn & 3) * 32 + (lane & 3) * 2;
#pragma unroll
    for (int mi = 0; mi < 4; mi++) {
        int node = node0 + wm * 64 + mi * 16 + (lane >> 2);
#pragma unroll
        for (int nf = 0; nf < 4; nf++) {
            int col = colbase + nf * 8;
            if (node < N)
                *(float2*)(dstbase + (size_t)node * NF + col)
                    = make_float2(acc[mi * 4 + nf][0], acc[mi * 4 + nf][1]);
            if (node + 8 < N)
                *(float2*)(dstbase + (size_t)(node + 8) * NF + col)
                    = make_float2(acc[mi * 4 + nf][2], acc[mi * 4 + nf][3]);
        }
    }
}

// ---------------- kernel E: fused attention + softmax + aggregation -----------
// Warp per dst node; 2-way edge unroll for load MLP.
__global__ void fused_agg_kernel(const void* __restrict__ ei, long long E,
                                 const float* __restrict__ x, const float* __restrict__ da,
                                 const float* __restrict__ bias, const float* __restrict__ pa,
                                 float* __restrict__ outf, int N) {
    const int is64 = g_is64;
    int lane = threadIdx.x & 31;
    int node = blockIdx.x * 8 + (threadIdx.x >> 5);
    if (node >= N) return;
    int b0 = g_base[node], b1 = g_base[node + 1];

    float4 dpv = ((const float4*)(g_dp + (size_t)node * NF))[lane];
    float4 wav = ((const float4*)da)[lane];

    float den = 0.0f;
    float4 acc = make_float4(0.f, 0.f, 0.f, 0.f);
    int j = b0;
    for (; j + 1 < b1; j += 2) {
        int e0 = g_bucket[j], e1 = g_bucket[j + 1];
        long long s0 = get_idx(ei, e0, is64);
        long long s1 = get_idx(ei, e1, is64);
        float4 v0 = ((const float4*)(g_sp + s0 * NF))[lane];
        float4 v1 = ((const float4*)(g_sp + s1 * NF))[lane];
        float a0, a1, p0, p1, t;
        t = v0.x + dpv.x; t = t >= 0.f ? t : 0.2f * t; p0  = t * wav.x;
        t = v0.y + dpv.y; t = t >= 0.f ? t : 0.2f * t; p0 += t * wav.y;
        t = v0.z + dpv.z; t = t >= 0.f ? t : 0.2f * t; p0 += t * wav.z;
        t = v0.w + dpv.w; t = t >= 0.f ? t : 0.2f * t; p0 += t * wav.w;
        t = v1.x + dpv.x; t = t >= 0.f ? t : 0.2f * t; p1  = t * wav.x;
        t = v1.y + dpv.y; t = t >= 0.f ? t : 0.2f * t; p1 += t * wav.y;
        t = v1.z + dpv.z; t = t >= 0.f ? t : 0.2f * t; p1 += t * wav.z;
        t = v1.w + dpv.w; t = t >= 0.f ? t : 0.2f * t; p1 += t * wav.w;
        p0 += __shfl_xor_sync(0xffffffffu, p0, 1);
        p1 += __shfl_xor_sync(0xffffffffu, p1, 1);
        p0 += __shfl_xor_sync(0xffffffffu, p0, 2);
        p1 += __shfl_xor_sync(0xffffffffu, p1, 2);
        p0 += __shfl_xor_sync(0xffffffffu, p0, 4);
        p1 += __shfl_xor_sync(0xffffffffu, p1, 4);
        a0 = __expf(p0);
        a1 = __expf(p1);
        den += a0 + a1;
        acc.x += v0.x * a0 + v1.x * a1;
        acc.y += v0.y * a0 + v1.y * a1;
        acc.z += v0.z * a0 + v1.z * a1;
        acc.w += v0.w * a0 + v1.w * a1;
    }
    if (j < b1) {
        int e = g_bucket[j];
        long long s = get_idx(ei, e, is64);
        float4 v = ((const float4*)(g_sp + s * NF))[lane];
        float t, p;
        t = v.x + dpv.x; t = t >= 0.f ? t : 0.2f * t; p  = t * wav.x;
        t = v.y + dpv.y; t = t >= 0.f ? t : 0.2f * t; p += t * wav.y;
        t = v.z + dpv.z; t = t >= 0.f ? t : 0.2f * t; p += t * wav.z;
        t = v.w + dpv.w; t = t >= 0.f ? t : 0.2f * t; p += t * wav.w;
        p += __shfl_xor_sync(0xffffffffu, p, 1);
        p += __shfl_xor_sync(0xffffffffu, p, 2);
        p += __shfl_xor_sync(0xffffffffu, p, 4);
        float ex = __expf(p);
        den += ex;
        acc.x += v.x * ex; acc.y += v.y * ex;
        acc.z += v.z * ex; acc.w += v.w * ex;
    }
    float inv = 1.0f / (den + 1e-16f);

    float4 xr = ((const float4*)(x + (size_t)node * NF))[lane];
    float4 bb = ((const float4*)bias)[lane];
    float a = pa[0];
    float4 o;
    o.x = acc.x * inv + xr.x + bb.x; o.x = o.x >= 0.f ? o.x : a * o.x;
    o.y = acc.y * inv + xr.y + bb.y; o.y = o.y >= 0.f ? o.y : a * o.y;
    o.z = acc.z * inv + xr.z + bb.z; o.z = o.z >= 0.f ? o.z : a * o.z;
    o.w = acc.w * inv + xr.w + bb.w; o.w = o.w >= 0.f ? o.w : a * o.w;
    ((float4*)(outf + (size_t)node * NF))[lane] = o;
}

// ---------------- launch -------------------------------------------------------
extern "C" void kernel_launch(void* const* d_in, const int* in_sizes, int n_in,
                              void* d_out, int out_size) {
    const float* x    = (const float*)d_in[0];
    const void*  ei   = d_in[1];
    const float* bw_s = (const float*)d_in[2];
    const float* sw_s = (const float*)d_in[3];
    const float* bw_d = (const float*)d_in[4];
    const float* sw_d = (const float*)d_in[5];
    const float* da   = (const float*)d_in[6];
    const float* bias = (const float*)d_in[7];
    const float* pa   = (const float*)d_in[8];
    float* outf = (float*)d_out;

    int       N = in_sizes[0] / NF;
    long long E = (long long)in_sizes[1] / 2;
    int nb = (N + 1023) / 1024;

    cudaFuncSetAttribute(proj_gemm_kernel, cudaFuncAttributeMaxDynamicSharedMemorySize, SMEM_BYTES);

    detect_kernel<<<1, 32>>>((const int*)ei, E);
    prep_xT_kernel<<<dim3((N + 31) / 32, 4), dim3(32, 8)>>>(x, N);
    prep_wt_kernel<<<(NIT * 256 * BPCOL + 255) / 256, 256>>>(bw_s, sw_s, bw_d, sw_d);
    count_kernel<<<(int)((E + 255) / 256), 256>>>(ei, E);
    scanA_kernel<<<nb, 1024>>>(N);
    scanC_kernel<<<nb, 1024>>>(N, nb);
    scatter_kernel<<<(int)((E + 255) / 256), 256>>>(ei, E);
    proj_gemm_kernel<<<(N + TILE_M - 1) / TILE_M, 512, SMEM_BYTES>>>(N);
    fused_agg_kernel<<<(N + 7) / 8, 256>>>(ei, E, x, da, bias, pa, outf, N);
}